// round 9
// baseline (speedup 1.0000x reference)
#include <cuda_runtime.h>
#include <cuda_bf16.h>
#include <math.h>
#include <stdint.h>

// ---------------------------------------------------------------------------
// Problem constants
// ---------------------------------------------------------------------------
namespace {
constexpr int BATCH = 8;
constexpr int HWD   = 128;
constexpr int DIM   = 256;
constexpr int NWIN  = 256;
constexpr int NTOK  = 64;
constexpr int LTOT  = BATCH * HWD * HWD;            // 131072
constexpr int QKV_ROWS = 2 * BATCH * NWIN * NTOK;   // 262144
constexpr int HID   = 512;
constexpr int GEMM_SMEM = 2 * 2 * 128 * 20 * 4;     // 40960 B
constexpr int ATTN_SMEM = (400 + 2*2560 + 2*1280) * 4; // 32320 B
}
#define QSCALE  0.17677669529663687f   /* 32^-0.5 */
#define LOG2E   1.4426950408889634f

// ---------------------------------------------------------------------------
// Scratch.  bf16 for tensors that feed ONLY MMA operands (zero extra error:
// they would be rounded to bf16 at MMA-pack time anyway).  fp32 for tensors
// consumed by fp32 math (g_qk -> gradv finite diffs, g_t -> gate conv, g_y).
// ---------------------------------------------------------------------------
__device__ __nv_bfloat16 g_xn [(size_t)LTOT * DIM];
__device__ float         g_qk [(size_t)QKV_ROWS * 256];
__device__ float         g_qg [(size_t)2*8*128*256];
__device__ float         g_kg [(size_t)2*8*128*256];
__device__ __nv_bfloat16 g_vt [(size_t)2*8*128*256*64];   // (p,b,c,win,tok)
__device__ __nv_bfloat16 g_ao [(size_t)QKV_ROWS * 128];
__device__ float         g_y  [(size_t)LTOT * DIM];
__device__ __nv_bfloat16 g_z  [(size_t)LTOT * DIM];
__device__ float         g_t  [(size_t)LTOT * HID];
__device__ __nv_bfloat16 g_g  [(size_t)LTOT * DIM];

// ---------------------------------------------------------------------------
// Window row -> spatial index (roll handled; self-inverse map)
// ---------------------------------------------------------------------------
__device__ __forceinline__ size_t spatial_idx(int r) {
    int p   = r >> 17;
    int rem = r & 131071;
    int b   = rem >> 14;
    int win = (rem >> 6) & 255;
    int t   = rem & 63;
    int hh  = ((win >> 4) << 3) + (t >> 3);
    int ww  = ((win & 15) << 3) + (t & 7);
    if (p) { hh = (hh + 4) & 127; ww = (ww + 4) & 127; }
    return ((size_t)(b * 16384 + hh * 128 + ww)) * 256 + p * 128;
}

// ---------------------------------------------------------------------------
// bf16 helpers
// ---------------------------------------------------------------------------
__device__ __forceinline__ uint32_t pack_bf16(float lo, float hi) {
    __nv_bfloat162 p = __floats2bfloat162_rn(lo, hi);
    return *reinterpret_cast<uint32_t*>(&p);
}
__device__ __forceinline__ void mma16(float* c, const uint32_t* a,
                                      uint32_t b0, uint32_t b1) {
    asm volatile(
        "mma.sync.aligned.m16n8k16.row.col.f32.bf16.bf16.f32 "
        "{%0,%1,%2,%3},{%4,%5,%6,%7},{%8,%9},{%0,%1,%2,%3};"
        : "+f"(c[0]), "+f"(c[1]), "+f"(c[2]), "+f"(c[3])
        : "r"(a[0]), "r"(a[1]), "r"(a[2]), "r"(a[3]), "r"(b0), "r"(b1));
}

// ---------------------------------------------------------------------------
// LayerNorm (bf16 out)
// ---------------------------------------------------------------------------
template <int MODE>
__global__ __launch_bounds__(256) void ln_kernel(
    const float* __restrict__ in_ext,
    const float* __restrict__ gamma, const float* __restrict__ beta)
{
    __shared__ float s1[8], s2[8];
    const float* in = (MODE == 0) ? in_ext : g_y;
    __nv_bfloat16* out = (MODE == 0) ? g_xn : g_z;
    size_t base = (size_t)blockIdx.x * 256;
    int tid = threadIdx.x;
    float v = in[base + tid];
    float a = v, q = v * v;
    #pragma unroll
    for (int o = 16; o > 0; o >>= 1) {
        a += __shfl_xor_sync(0xffffffffu, a, o);
        q += __shfl_xor_sync(0xffffffffu, q, o);
    }
    if ((tid & 31) == 0) { s1[tid >> 5] = a; s2[tid >> 5] = q; }
    __syncthreads();
    float suma = 0.f, sumq = 0.f;
    #pragma unroll
    for (int w = 0; w < 8; w++) { suma += s1[w]; sumq += s2[w]; }
    float mean = suma * (1.f / 256.f);
    float var  = sumq * (1.f / 256.f) - mean * mean;
    float inv  = rsqrtf(var + 1e-5f);
    out[base + tid] = __float2bfloat16((v - mean) * inv * gamma[tid] + beta[tid]);
}

// ---------------------------------------------------------------------------
// bf16 GEMM, double-buffered (1 bar/chunk). C = A @ W^T (+bias, +epilogue)
// A is bf16 in global (direct uint4 copies); W is f32 (packed at load).
// 128x128 tile, BK=32, 256 threads. Smem rows: 20 words.
// ---------------------------------------------------------------------------
enum { M_QKV = 0, M_PROJ = 1, M_FC2 = 2, M_FC1 = 3 };

#define ATS(b,m,k) dsm[(b)*2560 + (m)*20 + (k)]
#define BTS(b,m,k) dsm[5120 + (b)*2560 + (m)*20 + (k)]

template <int MODE, int K>
__global__ __launch_bounds__(256, 2) void gemm_tc(
    const float* __restrict__ Wt,
    const float* __restrict__ bias,
    const float* __restrict__ ext_in,
    float* __restrict__ ext_out)
{
    extern __shared__ uint32_t dsm[];
    const int tid = threadIdx.x, lane = tid & 31, warp = tid >> 5;
    const int wm = warp >> 1, wn = warp & 1;
    const int g = lane >> 2, tg = lane & 3;
    const int m0 = blockIdx.x * 128, n0 = blockIdx.y * 128;
    constexpr int NC = K / 32;

    const __nv_bfloat16* Abase =
        (MODE == M_PROJ) ? g_ao :
        (MODE == M_FC1)  ? g_z  :
        (MODE == M_FC2)  ? g_g  : (const __nv_bfloat16*)0;

    float c[2][8][4];
    #pragma unroll
    for (int mi = 0; mi < 2; mi++)
        #pragma unroll
        for (int ni = 0; ni < 8; ni++)
            #pragma unroll
            for (int k = 0; k < 4; k++) c[mi][ni][k] = 0.f;

    // A loads: thread -> (m = tid>>2 (+64), 8 k's at (tid&3)*8)
    const int am = tid >> 2, ak = (tid & 3) * 8;
    const __nv_bfloat16* arow[2];
    #pragma unroll
    for (int i = 0; i < 2; i++) {
        int m = am + 64 * i;
        arow[i] = (MODE == M_QKV) ? (g_xn + spatial_idx(m0 + m))
                                  : (Abase + (size_t)(m0 + m) * K);
    }
    // B loads: thread -> (n = tid>>3 (+32i), 4 k's at (tid&7)*4)
    const int lm = tid >> 3, lq = tid & 7;
    const float* brow[4];
    #pragma unroll
    for (int i = 0; i < 4; i++)
        brow[i] = Wt + (size_t)(n0 + lm + 32 * i) * K;

    uint4 pa[2];
    float4 pbf[4];
    #pragma unroll
    for (int i = 0; i < 2; i++)
        pa[i] = *(const uint4*)(arow[i] + ak);
    #pragma unroll
    for (int i = 0; i < 4; i++)
        pbf[i] = *(const float4*)(brow[i] + lq * 4);

    #pragma unroll
    for (int i = 0; i < 2; i++)
        *(uint4*)&ATS(0, am + 64 * i, (tid & 3) * 4) = pa[i];
    #pragma unroll
    for (int i = 0; i < 4; i++)
        *(uint2*)&BTS(0, lm + 32 * i, lq * 2) =
            make_uint2(pack_bf16(pbf[i].x, pbf[i].y), pack_bf16(pbf[i].z, pbf[i].w));
    __syncthreads();
    if (NC > 1) {
        #pragma unroll
        for (int i = 0; i < 2; i++)
            pa[i] = *(const uint4*)(arow[i] + 32 + ak);
        #pragma unroll
        for (int i = 0; i < 4; i++)
            pbf[i] = *(const float4*)(brow[i] + 32 + lq * 4);
    }

    for (int ic = 0; ic < NC; ic++) {
        int cur = ic & 1, nxt = cur ^ 1;
        if (ic < NC - 1) {
            #pragma unroll
            for (int i = 0; i < 2; i++)
                *(uint4*)&ATS(nxt, am + 64 * i, (tid & 3) * 4) = pa[i];
            #pragma unroll
            for (int i = 0; i < 4; i++)
                *(uint2*)&BTS(nxt, lm + 32 * i, lq * 2) =
                    make_uint2(pack_bf16(pbf[i].x, pbf[i].y), pack_bf16(pbf[i].z, pbf[i].w));
            if (ic < NC - 2) {
                int koff = (ic + 2) * 32;
                #pragma unroll
                for (int i = 0; i < 2; i++)
                    pa[i] = *(const uint4*)(arow[i] + koff + ak);
                #pragma unroll
                for (int i = 0; i < 4; i++)
                    pbf[i] = *(const float4*)(brow[i] + koff + lq * 4);
            }
        }
        #pragma unroll
        for (int ks = 0; ks < 2; ks++) {
            int wbase = ks * 8;
            uint32_t a[2][4];
            #pragma unroll
            for (int mi = 0; mi < 2; mi++) {
                int r = wm * 32 + mi * 16;
                a[mi][0] = ATS(cur, r + g,     wbase + tg);
                a[mi][1] = ATS(cur, r + 8 + g, wbase + tg);
                a[mi][2] = ATS(cur, r + g,     wbase + 4 + tg);
                a[mi][3] = ATS(cur, r + 8 + g, wbase + 4 + tg);
            }
            #pragma unroll
            for (int ni = 0; ni < 8; ni++) {
                int cb = wn * 64 + ni * 8;
                uint32_t b0 = BTS(cur, cb + g, wbase + tg);
                uint32_t b1 = BTS(cur, cb + g, wbase + 4 + tg);
                mma16(c[0][ni], a[0], b0, b1);
                mma16(c[1][ni], a[1], b0, b1);
            }
        }
        __syncthreads();
    }

    #pragma unroll
    for (int mi = 0; mi < 2; mi++) {
        int rr0 = m0 + wm * 32 + mi * 16 + g;
        int rr1 = rr0 + 8;
        size_t sp0 = 0, sp1 = 0;
        if (MODE == M_PROJ) { sp0 = spatial_idx(rr0); sp1 = spatial_idx(rr1); }
        size_t vb0 = 0, vb1 = 0;
        if (MODE == M_QKV && n0 == 256) {
            int pb0 = rr0 >> 14, w0 = (rr0 >> 6) & 255, t0 = rr0 & 63;
            int pb1 = rr1 >> 14, w1 = (rr1 >> 6) & 255, t1 = rr1 & 63;
            vb0 = (((size_t)pb0 * 128) * 256 + w0) * 64 + t0;
            vb1 = (((size_t)pb1 * 128) * 256 + w1) * 64 + t1;
        }
        #pragma unroll
        for (int ni = 0; ni < 8; ni++) {
            int col = n0 + wn * 64 + ni * 8 + 2 * tg;
            float2 bb = *(const float2*)(bias + col);
            float v00 = c[mi][ni][0] + bb.x, v01 = c[mi][ni][1] + bb.y;
            float v10 = c[mi][ni][2] + bb.x, v11 = c[mi][ni][3] + bb.y;
            if (MODE == M_QKV) {
                if (n0 < 256) {
                    *(float2*)&g_qk[(size_t)rr0 * 256 + col] = make_float2(v00, v01);
                    *(float2*)&g_qk[(size_t)rr1 * 256 + col] = make_float2(v10, v11);
                } else {
                    size_t cv = (size_t)(col - 256) * 16384;
                    g_vt[vb0 + cv]         = __float2bfloat16(v00);
                    g_vt[vb0 + cv + 16384] = __float2bfloat16(v01);
                    g_vt[vb1 + cv]         = __float2bfloat16(v10);
                    g_vt[vb1 + cv + 16384] = __float2bfloat16(v11);
                }
            } else if (MODE == M_PROJ) {
                size_t i0 = sp0 + col, i1 = sp1 + col;
                float2 s0 = *(const float2*)(ext_in + i0);
                float2 s1 = *(const float2*)(ext_in + i1);
                *(float2*)&g_y[i0] = make_float2(s0.x + v00, s0.y + v01);
                *(float2*)&g_y[i1] = make_float2(s1.x + v10, s1.y + v11);
            } else if (MODE == M_FC1) {
                *(float2*)&g_t[(size_t)rr0 * 512 + col] = make_float2(v00, v01);
                *(float2*)&g_t[(size_t)rr1 * 512 + col] = make_float2(v10, v11);
            } else { // M_FC2
                size_t i0 = (size_t)rr0 * 256 + col, i1 = (size_t)rr1 * 256 + col;
                float2 y0 = *(const float2*)&g_y[i0];
                float2 y1 = *(const float2*)&g_y[i1];
                *(float2*)&ext_out[i0] = make_float2(y0.x + v00, y0.y + v01);
                *(float2*)&ext_out[i1] = make_float2(y1.x + v10, y1.y + v11);
            }
        }
    }
}

// ---------------------------------------------------------------------------
// Grad scores (Q,K f32). One block per (p,b,win) = 4096 blocks.
// ---------------------------------------------------------------------------
__global__ __launch_bounds__(256) void gradv_kernel() {
    __shared__ float buf[64][130];
    int blk = blockIdx.x;
    int pb  = blk >> 8;
    int win = blk & 255;
    const float* qk = g_qk + (size_t)blk * 64 * 256;
    int tid = threadIdx.x;

    #pragma unroll
    for (int phase = 0; phase < 2; phase++) {
        for (int idx = tid; idx < 64*128; idx += 256)
            buf[idx >> 7][idx & 127] = qk[(size_t)(idx >> 7) * 256 + phase*128 + (idx & 127)];
        __syncthreads();
        if (tid < 128) {
            float s = 0.f;
            #pragma unroll
            for (int tr = 0; tr < 8; tr++)
                #pragma unroll
                for (int tc = 0; tc < 8; tc++) {
                    float v = buf[tr*8+tc][tid];
                    float l = tc ? buf[tr*8+tc-1][tid] : 0.f;
                    float u = tr ? buf[(tr-1)*8+tc][tid] : 0.f;
                    s += fabsf(v - l) + fabsf(v - u);
                }
            size_t o = ((size_t)pb * 128 + tid) * 256 + win;
            if (phase == 0) g_qg[o] = s * QSCALE;
            else            g_kg[o] = s;
        }
        __syncthreads();
    }
}

// ---------------------------------------------------------------------------
// bf16 tensor-core attention, double-buffered + V register prefetch.
// V is bf16 in global; outputs bf16.
// ---------------------------------------------------------------------------
#define WSM(b,r,j) dsm[400 + (b)*2560 + (r)*20 + (j)]
#define VSM(b,t,j) dsm[5520 + (b)*1280 + (t)*20 + (j)]

__global__ __launch_bounds__(256, 3) void attn_tc() {
    extern __shared__ uint32_t dsm[];
    float* kg_s = (float*)dsm;
    float* zrow = (float*)(dsm + 256);
    float* red  = (float*)(dsm + 384);
    int bx = blockIdx.x;
    int mhalf = bx & 1;
    int blk = bx >> 1;
    int c  = blk & 127;
    int pb = blk >> 7;
    int tid = threadIdx.x, lane = tid & 31, warp = tid >> 5;
    int g = lane >> 2, tg = lane & 3;
    const float* kg = g_kg + (size_t)blk * 256;
    const float* qg = g_qg + (size_t)blk * 256;
    const unsigned short* vs =
        (const unsigned short*)(g_vt + (size_t)blk * (256 * 64));

    float kv = kg[tid];
    kg_s[tid] = kv;
    float km = kv;
    #pragma unroll
    for (int o = 16; o > 0; o >>= 1)
        km = fmaxf(km, __shfl_xor_sync(0xffffffffu, km, o));
    if (lane == 0) red[warp] = km;
    __syncthreads();
    km = red[0];
    #pragma unroll
    for (int w = 1; w < 8; w++) km = fmaxf(km, red[w]);

    int erow  = tid >> 1;
    int ehalf = tid & 1;
    const int jp = tid >> 6;
    const int vt = tid & 63;
    float qg2 = qg[mhalf * 128 + erow] * LOG2E;
    float m2  = qg2 * km;
    float zacc = 0.f;

    float acc[8][4];
    #pragma unroll
    for (int ni = 0; ni < 8; ni++)
        #pragma unroll
        for (int k = 0; k < 4; k++) acc[ni][k] = 0.f;

    // prologue: chunk 0
    #pragma unroll
    for (int q8 = 0; q8 < 8; q8++) {
        int j0 = ehalf * 16 + q8 * 2;
        float w0 = exp2f(fmaf(qg2, kg_s[j0],     -m2));
        float w1 = exp2f(fmaf(qg2, kg_s[j0 + 1], -m2));
        zacc += w0 + w1;
        WSM(0, erow, ehalf * 8 + q8) = pack_bf16(w0, w1);
    }
    #pragma unroll
    for (int e = 0; e < 4; e++) {
        int j0 = e * 8 + jp * 2;
        uint32_t u0 = vs[(size_t)j0 * 64 + vt];
        uint32_t u1 = vs[(size_t)(j0 + 1) * 64 + vt];
        VSM(0, vt, e * 4 + jp) = u0 | (u1 << 16);
    }
    __syncthreads();

    unsigned short vreg[8];
    #pragma unroll
    for (int e = 0; e < 4; e++) {
        int j0 = 32 + e * 8 + jp * 2;
        vreg[e*2]   = vs[(size_t)j0 * 64 + vt];
        vreg[e*2+1] = vs[(size_t)(j0 + 1) * 64 + vt];
    }

    for (int ic = 0; ic < 8; ic++) {
        int cur = ic & 1, nxt = cur ^ 1;
        if (ic < 7) {
            #pragma unroll
            for (int e = 0; e < 4; e++)
                VSM(nxt, vt, e * 4 + jp) =
                    (uint32_t)vreg[e*2] | ((uint32_t)vreg[e*2+1] << 16);
            if (ic < 6) {
                int kcv = (ic + 2) * 32;
                #pragma unroll
                for (int e = 0; e < 4; e++) {
                    int j0 = kcv + e * 8 + jp * 2;
                    vreg[e*2]   = vs[(size_t)j0 * 64 + vt];
                    vreg[e*2+1] = vs[(size_t)(j0 + 1) * 64 + vt];
                }
            }
            int kcn = (ic + 1) * 32;
            #pragma unroll
            for (int q8 = 0; q8 < 8; q8++) {
                int j0 = kcn + ehalf * 16 + q8 * 2;
                float w0 = exp2f(fmaf(qg2, kg_s[j0],     -m2));
                float w1 = exp2f(fmaf(qg2, kg_s[j0 + 1], -m2));
                zacc += w0 + w1;
                WSM(nxt, erow, ehalf * 8 + q8) = pack_bf16(w0, w1);
            }
        }
        #pragma unroll
        for (int ks = 0; ks < 2; ks++) {
            int wbase = ks * 8;
            uint32_t a[4];
            int r = warp * 16;
            a[0] = WSM(cur, r + g,     wbase + tg);
            a[1] = WSM(cur, r + 8 + g, wbase + tg);
            a[2] = WSM(cur, r + g,     wbase + 4 + tg);
            a[3] = WSM(cur, r + 8 + g, wbase + 4 + tg);
            #pragma unroll
            for (int ni = 0; ni < 8; ni++) {
                uint32_t b0 = VSM(cur, ni * 8 + g, wbase + tg);
                uint32_t b1 = VSM(cur, ni * 8 + g, wbase + 4 + tg);
                mma16(acc[ni], a, b0, b1);
            }
        }
        __syncthreads();
    }

    zacc += __shfl_xor_sync(0xffffffffu, zacc, 1);
    if (ehalf == 0) zrow[erow] = zacc;
    __syncthreads();

    int r0l = warp * 16 + g, r1l = r0l + 8;
    float iz0 = 1.f / zrow[r0l];
    float iz1 = 1.f / zrow[r1l];
    int i0 = mhalf * 128 + r0l, i1 = mhalf * 128 + r1l;
    size_t ob0 = (((size_t)pb * 256 + i0) * 64) * 128 + c;
    size_t ob1 = (((size_t)pb * 256 + i1) * 64) * 128 + c;
    #pragma unroll
    for (int ni = 0; ni < 8; ni++) {
        int t = ni * 8 + 2 * tg;
        g_ao[ob0 + (size_t)t * 128]       = __float2bfloat16(acc[ni][0] * iz0);
        g_ao[ob0 + (size_t)(t + 1) * 128] = __float2bfloat16(acc[ni][1] * iz0);
        g_ao[ob1 + (size_t)t * 128]       = __float2bfloat16(acc[ni][2] * iz1);
        g_ao[ob1 + (size_t)(t + 1) * 128] = __float2bfloat16(acc[ni][3] * iz1);
    }
}

// ---------------------------------------------------------------------------
// Depthwise 3x3 + gate, sliding-column register window; bf16 out
// ---------------------------------------------------------------------------
__global__ __launch_bounds__(256) void gate_kernel(
    const float* __restrict__ dww, const float* __restrict__ dwb)
{
    int bh = blockIdx.x;
    int b  = bh >> 7;
    int hh = bh & 127;
    int c  = threadIdx.x;
    float w1[9], w2[9];
    #pragma unroll
    for (int k = 0; k < 9; k++) {
        w1[k] = dww[c*9 + k];
        w2[k] = dww[(c+256)*9 + k];
    }
    float b1 = dwb[c], b2 = dwb[c+256];
    const float* tb = g_t + (size_t)b * 16384 * 512;
    __nv_bfloat16* gout = g_g + ((size_t)b * 16384 + hh * 128) * 256 + c;

    float cA[3][3], cB[3][3];
    #pragma unroll
    for (int r = 0; r < 3; r++) { cA[0][r] = 0.f; cB[0][r] = 0.f; }
    #pragma unroll
    for (int r = 0; r < 3; r++) {
        int hy = hh - 1 + r;
        bool ok = (unsigned)hy < 128u;
        size_t off = ((size_t)hy * 128 + 0) * 512;
        cA[1][r] = ok ? tb[off + c]       : 0.f;
        cB[1][r] = ok ? tb[off + 256 + c] : 0.f;
        cA[2][r] = ok ? tb[off + 512 + c]       : 0.f;
        cB[2][r] = ok ? tb[off + 512 + 256 + c] : 0.f;
    }

    for (int ww = 0; ww < 128; ww++) {
        float s1 = b1, s2 = b2;
        #pragma unroll
        for (int r = 0; r < 3; r++) {
            s1 = fmaf(cA[0][r], w1[r*3+0], s1);
            s1 = fmaf(cA[1][r], w1[r*3+1], s1);
            s1 = fmaf(cA[2][r], w1[r*3+2], s1);
            s2 = fmaf(cB[0][r], w2[r*3+0], s2);
            s2 = fmaf(cB[1][r], w2[r*3+1], s2);
            s2 = fmaf(cB[2][r], w2[r*3+2], s2);
        }
        gout[(size_t)ww * 256] = __float2bfloat16(s1 * s2);
        int wx = ww + 2;
        bool okx = wx < 128;
        #pragma unroll
        for (int r = 0; r < 3; r++) {
            cA[0][r] = cA[1][r]; cA[1][r] = cA[2][r];
            cB[0][r] = cB[1][r]; cB[1][r] = cB[2][r];
            int hy = hh - 1 + r;
            bool ok = okx && (unsigned)hy < 128u;
            size_t off = ((size_t)hy * 128 + wx) * 512;
            cA[2][r] = ok ? tb[off + c]       : 0.f;
            cB[2][r] = ok ? tb[off + 256 + c] : 0.f;
        }
    }
}

// ---------------------------------------------------------------------------
// Launch (attribute calls unconditional — no static guards)
// ---------------------------------------------------------------------------
extern "C" void kernel_launch(void* const* d_in, const int* in_sizes, int n_in,
                              void* d_out, int out_size) {
    (void)in_sizes; (void)n_in; (void)out_size;
    const float* x     = (const float*)d_in[0];
    const float* n1g   = (const float*)d_in[1];
    const float* n1b   = (const float*)d_in[2];
    const float* qkvw  = (const float*)d_in[3];
    const float* qkvb  = (const float*)d_in[4];
    const float* projw = (const float*)d_in[5];
    const float* projb = (const float*)d_in[6];
    const float* n2g   = (const float*)d_in[7];
    const float* n2b   = (const float*)d_in[8];
    const float* fc1w  = (const float*)d_in[9];
    const float* fc1b  = (const float*)d_in[10];
    const float* dww   = (const float*)d_in[11];
    const float* dwb   = (const float*)d_in[12];
    const float* fc2w  = (const float*)d_in[13];
    const float* fc2b  = (const float*)d_in[14];
    float* out = (float*)d_out;

    cudaFuncSetAttribute(gemm_tc<M_QKV,128>,  cudaFuncAttributeMaxDynamicSharedMemorySize, GEMM_SMEM);
    cudaFuncSetAttribute(gemm_tc<M_PROJ,128>, cudaFuncAttributeMaxDynamicSharedMemorySize, GEMM_SMEM);
    cudaFuncSetAttribute(gemm_tc<M_FC1,256>,  cudaFuncAttributeMaxDynamicSharedMemorySize, GEMM_SMEM);
    cudaFuncSetAttribute(gemm_tc<M_FC2,256>,  cudaFuncAttributeMaxDynamicSharedMemorySize, GEMM_SMEM);
    cudaFuncSetAttribute(attn_tc,             cudaFuncAttributeMaxDynamicSharedMemorySize, ATTN_SMEM);

    ln_kernel<0><<<LTOT, 256>>>(x, n1g, n1b);
    gemm_tc<M_QKV, 128><<<dim3(QKV_ROWS/128, 3), 256, GEMM_SMEM>>>(qkvw, qkvb, (const float*)0, (float*)0);
    gradv_kernel<<<2*BATCH*NWIN, 256>>>();
    attn_tc<<<2*BATCH*128*2, 256, ATTN_SMEM>>>();
    gemm_tc<M_PROJ, 128><<<dim3(QKV_ROWS/128, 1), 256, GEMM_SMEM>>>(projw, projb, x, (float*)0);
    ln_kernel<1><<<LTOT, 256>>>((const float*)0, n2g, n2b);
    gemm_tc<M_FC1, 256><<<dim3(LTOT/128, 4), 256, GEMM_SMEM>>>(fc1w, fc1b, (const float*)0, (float*)0);
    gate_kernel<<<BATCH*HWD, 256>>>(dww, dwb);
    gemm_tc<M_FC2, 256><<<dim3(LTOT/128, 2), 256, GEMM_SMEM>>>(fc2w, fc2b, (const float*)0, out);
}